// round 13
// baseline (speedup 1.0000x reference)
#include <cuda_runtime.h>

#define N_ 1024
#define F_ 64
#define C_ 4
#define E_ 32768
#define H_ 256

// ---------------- scratch (device globals; no runtime allocation) ----------
__device__ float g_a[N_ * N_ * C_];   // a[i][j][c]  (i=src, j=tgt)  16 MB
__device__ float g_h[N_ * H_];        // stage-1 concat features [n][c*64+f]
__device__ float g_hid[N_ * H_];      // stage-1 hidden
__device__ float g_xn[N_ * F_];       // x_next
__device__ float g_P[N_ * H_];        // be1 + x_next @ We1[rows 4..67]
__device__ float g_Q[N_ * H_];        //       x_next @ We1[rows 68..131]

// ---------------- f32x2 helpers --------------------------------------------
__device__ __forceinline__ unsigned long long pack2(float x, float y) {
    unsigned long long r;
    asm("mov.b64 %0, {%1,%2};" : "=l"(r) : "r"(__float_as_uint(x)), "r"(__float_as_uint(y)));
    return r;
}
__device__ __forceinline__ void fma2(unsigned long long& acc, unsigned long long a,
                                     unsigned long long b) {
    asm("fma.rn.f32x2 %0, %1, %2, %0;" : "+l"(acc) : "l"(a), "l"(b));
}
__device__ __forceinline__ float lo_f(unsigned long long v) {
    return __uint_as_float((unsigned)(v & 0xffffffffull));
}
__device__ __forceinline__ float hi_f(unsigned long long v) {
    return __uint_as_float((unsigned)(v >> 32));
}

// ---------------- 1. zero dense adjacency ----------------------------------
__global__ void k_zero_a() {
    int idx = blockIdx.x * 256 + threadIdx.x;       // 1M float4s
    reinterpret_cast<float4*>(g_a)[idx] = make_float4(0.f, 0.f, 0.f, 0.f);
}

// ---------------- 2. scatter edges into dense a ----------------------------
__global__ void k_scatter(const int* __restrict__ ei, const float* __restrict__ ew) {
    int idx = blockIdx.x * 256 + threadIdx.x;       // < C*E = 131072
    int c = idx >> 15;                              // E = 2^15
    int e = idx & (E_ - 1);
    int s = ei[c * 2 * E_ + e];                     // edge_index[c][0][e] = src
    int t = ei[c * 2 * E_ + E_ + e];                // edge_index[c][1][e] = tgt
    float w = ew[c * E_ + e];
    atomicAdd(&g_a[(s * N_ + t) * C_ + c], w);
}

// ---------------- 3. agg[c][t][f] = sum_s a[s][t][c] * x[s][f]; + self -----
// Block: 16 targets. Thread tid: c = tid>>6, f = tid&63.
__global__ void __launch_bounds__(256) k_agg(const float* __restrict__ x,
                                             const float* __restrict__ eps_p) {
    __shared__ float as[64][64];   // [ss][t_local*4 + c]
    __shared__ float xs[64][64];   // [ss][f]
    int tid = threadIdx.x;
    int c = tid >> 6, f = tid & 63;
    int t0 = blockIdx.x * 16;
    float acc[16];
#pragma unroll
    for (int tt = 0; tt < 16; tt++) acc[tt] = 0.f;

    for (int s0 = 0; s0 < N_; s0 += 64) {
#pragma unroll
        for (int m = 0; m < 16; m++) {
            int idx = m * 256 + tid;               // 0..4095
            int ss = idx >> 6, q = idx & 63;
            as[ss][q] = g_a[((s0 + ss) * N_ + t0 + (q >> 2)) * C_ + (q & 3)];
            xs[ss][q] = x[(s0 + ss) * F_ + q];
        }
        __syncthreads();
        for (int ss = 0; ss < 64; ss++) {
            float xv = xs[ss][f];
#pragma unroll
            for (int tt = 0; tt < 16; tt++)
                acc[tt] += as[ss][tt * 4 + c] * xv;
        }
        __syncthreads();
    }
    float se = 1.0f + *eps_p;
#pragma unroll
    for (int tt = 0; tt < 16; tt++)
        g_h[(t0 + tt) * H_ + c * F_ + f] = acc[tt] + se * x[(t0 + tt) * F_ + f];
}

// ---------------- 4. hid = relu(h @ Wn1 + bn1) ------------------------------
__global__ void __launch_bounds__(256) k_mlp1(const float* __restrict__ Wn1,
                                              const float* __restrict__ bn1) {
    __shared__ float hs[16][256];
    int tid = threadIdx.x;
    int n0 = blockIdx.x * 16;
#pragma unroll
    for (int m = 0; m < 16; m++) hs[m][tid] = g_h[(n0 + m) * 256 + tid];
    __syncthreads();
    float acc[16];
#pragma unroll
    for (int nn = 0; nn < 16; nn++) acc[nn] = 0.f;
    for (int k = 0; k < 256; k++) {
        float w = Wn1[k * 256 + tid];
#pragma unroll
        for (int nn = 0; nn < 16; nn++) acc[nn] += hs[nn][k] * w;
    }
    float b = bn1[tid];
#pragma unroll
    for (int nn = 0; nn < 16; nn++)
        g_hid[(n0 + nn) * 256 + tid] = fmaxf(acc[nn] + b, 0.f);
}

// ---------------- 5. x_next = hid @ Wn2 + bn2 -------------------------------
__global__ void __launch_bounds__(256) k_mlp2(const float* __restrict__ Wn2,
                                              const float* __restrict__ bn2) {
    __shared__ float hs[16][256];
    int tid = threadIdx.x;
    int f = tid & 63, ng = tid >> 6;               // 4 groups x 4 rows
    int n0 = blockIdx.x * 16;
#pragma unroll
    for (int m = 0; m < 16; m++) hs[m][tid] = g_hid[(n0 + m) * 256 + tid];
    __syncthreads();
    float acc[4] = {0.f, 0.f, 0.f, 0.f};
    for (int k = 0; k < 256; k++) {
        float w = Wn2[k * 64 + f];
#pragma unroll
        for (int nn = 0; nn < 4; nn++) acc[nn] += hs[ng * 4 + nn][k] * w;
    }
    float b = bn2[f];
#pragma unroll
    for (int nn = 0; nn < 4; nn++)
        g_xn[(n0 + ng * 4 + nn) * 64 + f] = acc[nn] + b;
}

// ---------------- 6. P = be1 + xn@We1[4:68]; Q = xn@We1[68:132] -------------
__global__ void __launch_bounds__(256) k_pq(const float* __restrict__ We1,
                                            const float* __restrict__ be1) {
    __shared__ float xs[16][64];
    int tid = threadIdx.x;
    int n0 = blockIdx.x * 16;
#pragma unroll
    for (int m = 0; m < 4; m++) {
        int idx = m * 256 + tid;                   // 0..1023
        xs[idx >> 6][idx & 63] = g_xn[n0 * 64 + idx];
    }
    __syncthreads();
    float aP[16], aQ[16];
#pragma unroll
    for (int nn = 0; nn < 16; nn++) { aP[nn] = 0.f; aQ[nn] = 0.f; }
    for (int f = 0; f < 64; f++) {
        float w1 = We1[(4 + f) * 256 + tid];
        float w2 = We1[(68 + f) * 256 + tid];
#pragma unroll
        for (int nn = 0; nn < 16; nn++) {
            float xv = xs[nn][f];
            aP[nn] += xv * w1;
            aQ[nn] += xv * w2;
        }
    }
    float b = be1[tid];
#pragma unroll
    for (int nn = 0; nn < 16; nn++) {
        g_P[(n0 + nn) * 256 + tid] = aP[nn] + b;
        g_Q[(n0 + nn) * 256 + tid] = aQ[nn];
    }
}

// ---------------- 7. dense pass: out[i,j,:] = relu(P_i+Q_j) @ We2 + be2 -----
#define PSTR 258   // padded row stride (floats): 8B aligned, <=2-way conflicts
__global__ void __launch_bounds__(256) k_dense(const float* __restrict__ We2,
                                               const float* __restrict__ be2,
                                               float* __restrict__ out) {
    extern __shared__ float sm[];
    float* Ps = sm;                                 // 32 * 258
    float* Qs = sm + 32 * PSTR;                     // 32 * 258
    unsigned long long* W2p =
        (unsigned long long*)(sm + 2 * 32 * PSTR);  // 128 h2 x 4 o
    int tid = threadIdx.x;
    int ibase = blockIdx.x * 32, jbase = blockIdx.y * 32;

#pragma unroll
    for (int m = 0; m < 32; m++) {
        int idx = m * 256 + tid;                    // 0..8191
        int r = idx >> 8, k = idx & 255;
        Ps[r * PSTR + k] = g_P[(ibase + r) * 256 + k];
        Qs[r * PSTR + k] = g_Q[(jbase + r) * 256 + k];
    }
    for (int u = tid; u < 512; u += 256) {
        int h2 = u >> 2, o = u & 3;
        W2p[u] = pack2(We2[(2 * h2) * 4 + o], We2[(2 * h2 + 1) * 4 + o]);
    }
    __syncthreads();

    int jg = tid & 15, ig = tid >> 4;               // 2 i's x 2 j's per thread
    const float2* PA = (const float2*)(Ps + (2 * ig) * PSTR);
    const float2* PB = (const float2*)(Ps + (2 * ig + 1) * PSTR);
    const float2* QA = (const float2*)(Qs + (2 * jg) * PSTR);
    const float2* QB = (const float2*)(Qs + (2 * jg + 1) * PSTR);

    unsigned long long acc[4][4];                   // [pair 2*di+dj][o]
    unsigned long long z = pack2(0.f, 0.f);
#pragma unroll
    for (int p = 0; p < 4; p++)
#pragma unroll
        for (int o = 0; o < 4; o++) acc[p][o] = z;

#pragma unroll 4
    for (int h2 = 0; h2 < 128; h2++) {
        float2 pa = PA[h2], pb = PB[h2], qa = QA[h2], qb = QB[h2];
        unsigned long long w0 = W2p[h2 * 4 + 0];
        unsigned long long w1 = W2p[h2 * 4 + 1];
        unsigned long long w2 = W2p[h2 * 4 + 2];
        unsigned long long w3 = W2p[h2 * 4 + 3];
#define DO_PAIR(PV, QV, A)                                          \
        {                                                           \
            float rx = fmaxf(PV.x + QV.x, 0.f);                     \
            float ry = fmaxf(PV.y + QV.y, 0.f);                     \
            unsigned long long r2 = pack2(rx, ry);                  \
            fma2(A[0], r2, w0); fma2(A[1], r2, w1);                 \
            fma2(A[2], r2, w2); fma2(A[3], r2, w3);                 \
        }
        DO_PAIR(pa, qa, acc[0]);
        DO_PAIR(pa, qb, acc[1]);
        DO_PAIR(pb, qa, acc[2]);
        DO_PAIR(pb, qb, acc[3]);
#undef DO_PAIR
    }

    float b0 = be2[0], b1 = be2[1], b2v = be2[2], b3 = be2[3];
#pragma unroll
    for (int di = 0; di < 2; di++)
#pragma unroll
        for (int dj = 0; dj < 2; dj++) {
            int p = di * 2 + dj;
            int gi = ibase + 2 * ig + di;
            int gj = jbase + 2 * jg + dj;
            float4 r;
            r.x = lo_f(acc[p][0]) + hi_f(acc[p][0]) + b0;
            r.y = lo_f(acc[p][1]) + hi_f(acc[p][1]) + b1;
            r.z = lo_f(acc[p][2]) + hi_f(acc[p][2]) + b2v;
            r.w = lo_f(acc[p][3]) + hi_f(acc[p][3]) + b3;
            *reinterpret_cast<float4*>(out + ((size_t)gi * N_ + gj) * 4) = r;
        }
}

// ---------------- 8. fixup: recompute every edge-touched cell with its a ----
// One warp per (c,e) edge instance. Duplicates rewrite identical values.
__global__ void __launch_bounds__(256) k_fixup(const int* __restrict__ ei,
                                               const float* __restrict__ We1,
                                               const float* __restrict__ We2,
                                               const float* __restrict__ be2,
                                               float* __restrict__ out) {
    __shared__ float W1c[4][256];   // We1 rows 0..3 (a coefficients)
    __shared__ float W2T[4][256];   // We2 transposed
    int tid = threadIdx.x;
#pragma unroll
    for (int m = 0; m < 4; m++) {
        int idx = m * 256 + tid;                    // 0..1023
        W1c[idx >> 8][idx & 255] = We1[idx];        // first 4*256 floats of We1
        W2T[idx >> 8][idx & 255] = We2[(idx & 255) * 4 + (idx >> 8)];
    }
    __syncthreads();

    int w = tid >> 5, lane = tid & 31;
    int eidx = blockIdx.x * 8 + w;                  // < 131072
    int c = eidx >> 15;
    int e = eidx & (E_ - 1);
    int i = ei[c * 2 * E_ + e];
    int j = ei[c * 2 * E_ + E_ + e];

    float4 a4 = *reinterpret_cast<const float4*>(g_a + (i * N_ + j) * 4);
    const float* Pr = g_P + i * 256;
    const float* Qr = g_Q + j * 256;

    float a0 = 0.f, a1 = 0.f, a2 = 0.f, a3 = 0.f;
#pragma unroll
    for (int hh = 0; hh < 8; hh++) {
        int h = hh * 32 + lane;
        float t = Pr[h] + Qr[h]
                + a4.x * W1c[0][h] + a4.y * W1c[1][h]
                + a4.z * W1c[2][h] + a4.w * W1c[3][h];
        t = fmaxf(t, 0.f);
        a0 += t * W2T[0][h];
        a1 += t * W2T[1][h];
        a2 += t * W2T[2][h];
        a3 += t * W2T[3][h];
    }
#pragma unroll
    for (int off = 16; off > 0; off >>= 1) {
        a0 += __shfl_xor_sync(0xffffffffu, a0, off);
        a1 += __shfl_xor_sync(0xffffffffu, a1, off);
        a2 += __shfl_xor_sync(0xffffffffu, a2, off);
        a3 += __shfl_xor_sync(0xffffffffu, a3, off);
    }
    if (lane == 0) {
        float4 r = make_float4(a0 + be2[0], a1 + be2[1], a2 + be2[2], a3 + be2[3]);
        *reinterpret_cast<float4*>(out + ((size_t)i * N_ + j) * 4) = r;
    }
}

// ---------------- launch ----------------------------------------------------
extern "C" void kernel_launch(void* const* d_in, const int* in_sizes, int n_in,
                              void* d_out, int out_size) {
    const float* x   = (const float*)d_in[0];
    const int*   ei  = (const int*)  d_in[1];
    const float* ew  = (const float*)d_in[2];
    const float* Wn1 = (const float*)d_in[3];
    const float* bn1 = (const float*)d_in[4];
    const float* Wn2 = (const float*)d_in[5];
    const float* bn2 = (const float*)d_in[6];
    const float* We1 = (const float*)d_in[7];
    const float* be1 = (const float*)d_in[8];
    const float* We2 = (const float*)d_in[9];
    const float* be2 = (const float*)d_in[10];
    const float* eps = (const float*)d_in[11];
    float* out = (float*)d_out;

    const int DENSE_SMEM = (2 * 32 * PSTR) * 4 + 512 * 8;   // 70144 bytes
    cudaFuncSetAttribute(k_dense, cudaFuncAttributeMaxDynamicSharedMemorySize,
                         DENSE_SMEM);

    k_zero_a<<<(N_ * N_ * C_ / 4) / 256, 256>>>();
    k_scatter<<<(C_ * E_) / 256, 256>>>(ei, ew);
    k_agg<<<N_ / 16, 256>>>(x, eps);
    k_mlp1<<<N_ / 16, 256>>>(Wn1, bn1);
    k_mlp2<<<N_ / 16, 256>>>(Wn2, bn2);
    k_pq<<<N_ / 16, 256>>>(We1, be1);
    k_dense<<<dim3(N_ / 32, N_ / 32), 256, DENSE_SMEM>>>(We2, be2, out);
    k_fixup<<<(C_ * E_) / 8, 256>>>(ei, We1, We2, be2, out);
}

// round 14
// speedup vs baseline: 1.3550x; 1.3550x over previous
#include <cuda_runtime.h>

#define N_ 1024
#define F_ 64
#define C_ 4
#define E_ 32768
#define H_ 256

typedef unsigned long long ull;

// ---------------- scratch (device globals; no runtime allocation) ----------
__device__ float g_a[N_ * N_ * C_];   // a[i][j][c]  (i=src, j=tgt)  16 MB
__device__ float g_h[N_ * H_];        // stage-1 concat features [n][c*64+f]
__device__ float g_P[N_ * H_];        // be1 + x_next @ We1[rows 4..67]
__device__ float g_Q[N_ * H_];        //       x_next @ We1[rows 68..131]

// ---------------- f32x2 helpers --------------------------------------------
__device__ __forceinline__ ull pack2(float x, float y) {
    ull r;
    asm("mov.b64 %0, {%1,%2};" : "=l"(r) : "r"(__float_as_uint(x)), "r"(__float_as_uint(y)));
    return r;
}
__device__ __forceinline__ void fma2(ull& acc, ull a, ull b) {
    asm("fma.rn.f32x2 %0, %1, %2, %0;" : "+l"(acc) : "l"(a), "l"(b));
}
__device__ __forceinline__ float lo_f(ull v) {
    return __uint_as_float((unsigned)(v & 0xffffffffull));
}
__device__ __forceinline__ float hi_f(ull v) {
    return __uint_as_float((unsigned)(v >> 32));
}

// ---------------- 1. zero dense adjacency ----------------------------------
__global__ void k_zero_a() {
    int idx = blockIdx.x * 256 + threadIdx.x;       // 1M float4s
    reinterpret_cast<float4*>(g_a)[idx] = make_float4(0.f, 0.f, 0.f, 0.f);
}

// ---------------- 2. scatter edges into dense a ----------------------------
__global__ void k_scatter(const int* __restrict__ ei, const float* __restrict__ ew) {
    int idx = blockIdx.x * 256 + threadIdx.x;       // < C*E = 131072
    int c = idx >> 15;                              // E = 2^15
    int e = idx & (E_ - 1);
    int s = ei[c * 2 * E_ + e];                     // edge_index[c][0][e] = src
    int t = ei[c * 2 * E_ + E_ + e];                // edge_index[c][1][e] = tgt
    float w = ew[c * E_ + e];
    atomicAdd(&g_a[(s * N_ + t) * C_ + c], w);
}

// ---------------- 3. agg[c][t][f] = sum_s a[s][t][c] * x[s][f]; + self -----
// 128 blocks x 8 targets. Thread: c = tid>>6, f = tid&63. FFMA2 over
// target-pairs; all compute-loop smem reads are warp-broadcast.
__global__ void __launch_bounds__(256) k_agg(const float* __restrict__ x,
                                             const float* __restrict__ eps_p) {
    __shared__ __align__(16) float as[64][32];   // [ss][c*8 + t_local]
    __shared__ __align__(16) float xs[64][64];   // [ss][f]
    int tid = threadIdx.x;
    int c = tid >> 6, f = tid & 63;
    int t0 = blockIdx.x * 8;

    ull acc[4];
    ull z = pack2(0.f, 0.f);
#pragma unroll
    for (int j = 0; j < 4; j++) acc[j] = z;

    for (int s0 = 0; s0 < N_; s0 += 64) {
#pragma unroll
        for (int m = 0; m < 8; m++) {
            int elem = m * 256 + tid;              // 0..2047
            int ss = elem >> 5, q = elem & 31;
            // q = cL*8 + tl  ->  one 128B line per warp in g_a
            as[ss][q] = g_a[((s0 + ss) * N_ + t0 + (q & 7)) * 4 + (q >> 3)];
        }
#pragma unroll
        for (int m = 0; m < 16; m++) {
            int elem = m * 256 + tid;              // 0..4095
            xs[elem >> 6][elem & 63] = x[(s0 + (elem >> 6)) * 64 + (elem & 63)];
        }
        __syncthreads();
#pragma unroll 8
        for (int ss = 0; ss < 64; ss++) {
            float xv = xs[ss][f];
            ull xv2 = pack2(xv, xv);
            const ull* ap = (const ull*)&as[ss][c * 8];
            fma2(acc[0], ap[0], xv2);
            fma2(acc[1], ap[1], xv2);
            fma2(acc[2], ap[2], xv2);
            fma2(acc[3], ap[3], xv2);
        }
        __syncthreads();
    }
    float se = 1.0f + *eps_p;
#pragma unroll
    for (int j = 0; j < 4; j++) {
        int t = t0 + 2 * j;
        g_h[t * 256 + c * 64 + f]       = lo_f(acc[j]) + se * x[t * 64 + f];
        g_h[(t + 1) * 256 + c * 64 + f] = hi_f(acc[j]) + se * x[(t + 1) * 64 + f];
    }
}

// ---------------- 4. fused node MLP: hid=relu(h@Wn1+bn1); xn=hid@Wn2+bn2;
//                     P=be1+xn@We1[4:68]; Q=xn@We1[68:132] --------------------
// 128 blocks x 8 rows. Row-transposed smem (pad 10 floats keeps 8B alignment);
// all compute-loop smem reads are warp-broadcast, so padding conflicts only
// affect the cheap transpose stores.
__global__ void __launch_bounds__(256) k_node(const float* __restrict__ Wn1,
                                              const float* __restrict__ bn1,
                                              const float* __restrict__ Wn2,
                                              const float* __restrict__ bn2,
                                              const float* __restrict__ We1,
                                              const float* __restrict__ be1) {
    __shared__ __align__(16) float hT[256][10];    // h transposed: [k][row]
    __shared__ __align__(16) float hidT[256][10];  // hidden transposed
    __shared__ __align__(16) float xT[64][10];     // x_next transposed: [f][row]
    int tid = threadIdx.x;
    int n0 = blockIdx.x * 8;

    // load + transpose h rows
#pragma unroll
    for (int m = 0; m < 8; m++) {
        int elem = m * 256 + tid;
        int r = elem >> 8, k = elem & 255;
        hT[k][r] = g_h[(n0 + r) * 256 + k];
    }
    __syncthreads();

    // ---- stage 1: hid = relu(h @ Wn1 + bn1), output h-index = tid ----
    {
        ull acc[4];
        ull z = pack2(0.f, 0.f);
#pragma unroll
        for (int j = 0; j < 4; j++) acc[j] = z;
#pragma unroll 8
        for (int k = 0; k < 256; k++) {
            float w = Wn1[k * 256 + tid];
            ull w2 = pack2(w, w);
            const ull* hp = (const ull*)&hT[k][0];
            fma2(acc[0], hp[0], w2);
            fma2(acc[1], hp[1], w2);
            fma2(acc[2], hp[2], w2);
            fma2(acc[3], hp[3], w2);
        }
        float b = bn1[tid];
#pragma unroll
        for (int j = 0; j < 4; j++) {
            hidT[tid][2 * j]     = fmaxf(lo_f(acc[j]) + b, 0.f);
            hidT[tid][2 * j + 1] = fmaxf(hi_f(acc[j]) + b, 0.f);
        }
    }
    __syncthreads();

    // ---- stage 2: x_next = hid @ Wn2 + bn2; thread owns (f, row-pair) ----
    {
        int f = tid & 63, pg = tid >> 6;           // pg uniform per warp
        ull acc = pack2(0.f, 0.f);
#pragma unroll 8
        for (int k = 0; k < 256; k++) {
            float w = Wn2[k * 64 + f];
            ull w2 = pack2(w, w);
            const ull* hp = (const ull*)&hidT[k][2 * pg];
            fma2(acc, hp[0], w2);
        }
        float b = bn2[f];
        xT[f][2 * pg]     = lo_f(acc) + b;
        xT[f][2 * pg + 1] = hi_f(acc) + b;
    }
    __syncthreads();

    // ---- stage 3: P = be1 + xn@We1[4:68]; Q = xn@We1[68:132]; h-index=tid ----
    {
        ull aP[4], aQ[4];
        ull z = pack2(0.f, 0.f);
#pragma unroll
        for (int j = 0; j < 4; j++) { aP[j] = z; aQ[j] = z; }
#pragma unroll 8
        for (int f = 0; f < 64; f++) {
            float w1 = We1[(4 + f) * 256 + tid];
            float wq = We1[(68 + f) * 256 + tid];
            ull w1p = pack2(w1, w1);
            ull wqp = pack2(wq, wq);
            const ull* xp = (const ull*)&xT[f][0];
#pragma unroll
            for (int j = 0; j < 4; j++) {
                fma2(aP[j], xp[j], w1p);
                fma2(aQ[j], xp[j], wqp);
            }
        }
        float b = be1[tid];
#pragma unroll
        for (int j = 0; j < 4; j++) {
            g_P[(n0 + 2 * j) * 256 + tid]     = lo_f(aP[j]) + b;
            g_P[(n0 + 2 * j + 1) * 256 + tid] = hi_f(aP[j]) + b;
            g_Q[(n0 + 2 * j) * 256 + tid]     = lo_f(aQ[j]);
            g_Q[(n0 + 2 * j + 1) * 256 + tid] = hi_f(aQ[j]);
        }
    }
}

// ---------------- 5. dense pass: out[i,j,:] = relu(P_i+Q_j) @ We2 + be2 -----
#define PSTR 258   // padded row stride (floats): 8B aligned, <=2-way conflicts
__global__ void __launch_bounds__(256) k_dense(const float* __restrict__ We2,
                                               const float* __restrict__ be2,
                                               float* __restrict__ out) {
    extern __shared__ float sm[];
    float* Ps = sm;                                 // 32 * 258
    float* Qs = sm + 32 * PSTR;                     // 32 * 258
    ull* W2p = (ull*)(sm + 2 * 32 * PSTR);          // 128 h2 x 4 o
    int tid = threadIdx.x;
    int ibase = blockIdx.x * 32, jbase = blockIdx.y * 32;

#pragma unroll
    for (int m = 0; m < 32; m++) {
        int idx = m * 256 + tid;                    // 0..8191
        int r = idx >> 8, k = idx & 255;
        Ps[r * PSTR + k] = g_P[(ibase + r) * 256 + k];
        Qs[r * PSTR + k] = g_Q[(jbase + r) * 256 + k];
    }
    for (int u = tid; u < 512; u += 256) {
        int h2 = u >> 2, o = u & 3;
        W2p[u] = pack2(We2[(2 * h2) * 4 + o], We2[(2 * h2 + 1) * 4 + o]);
    }
    __syncthreads();

    int jg = tid & 15, ig = tid >> 4;               // 2 i's x 2 j's per thread
    const float2* PA = (const float2*)(Ps + (2 * ig) * PSTR);
    const float2* PB = (const float2*)(Ps + (2 * ig + 1) * PSTR);
    const float2* QA = (const float2*)(Qs + (2 * jg) * PSTR);
    const float2* QB = (const float2*)(Qs + (2 * jg + 1) * PSTR);

    ull acc[4][4];                                  // [pair 2*di+dj][o]
    ull z = pack2(0.f, 0.f);
#pragma unroll
    for (int p = 0; p < 4; p++)
#pragma unroll
        for (int o = 0; o < 4; o++) acc[p][o] = z;

#pragma unroll 4
    for (int h2 = 0; h2 < 128; h2++) {
        float2 pa = PA[h2], pb = PB[h2], qa = QA[h2], qb = QB[h2];
        ull w0 = W2p[h2 * 4 + 0];
        ull w1 = W2p[h2 * 4 + 1];
        ull w2 = W2p[h2 * 4 + 2];
        ull w3 = W2p[h2 * 4 + 3];
#define DO_PAIR(PV, QV, A)                                          \
        {                                                           \
            float rx = fmaxf(PV.x + QV.x, 0.f);                     \
            float ry = fmaxf(PV.y + QV.y, 0.f);                     \
            ull r2 = pack2(rx, ry);                                 \
            fma2(A[0], r2, w0); fma2(A[1], r2, w1);                 \
            fma2(A[2], r2, w2); fma2(A[3], r2, w3);                 \
        }
        DO_PAIR(pa, qa, acc[0]);
        DO_PAIR(pa, qb, acc[1]);
        DO_PAIR(pb, qa, acc[2]);
        DO_PAIR(pb, qb, acc[3]);
#undef DO_PAIR
    }

    float b0 = be2[0], b1 = be2[1], b2v = be2[2], b3 = be2[3];
#pragma unroll
    for (int di = 0; di < 2; di++)
#pragma unroll
        for (int dj = 0; dj < 2; dj++) {
            int p = di * 2 + dj;
            int gi = ibase + 2 * ig + di;
            int gj = jbase + 2 * jg + dj;
            float4 r;
            r.x = lo_f(acc[p][0]) + hi_f(acc[p][0]) + b0;
            r.y = lo_f(acc[p][1]) + hi_f(acc[p][1]) + b1;
            r.z = lo_f(acc[p][2]) + hi_f(acc[p][2]) + b2v;
            r.w = lo_f(acc[p][3]) + hi_f(acc[p][3]) + b3;
            *reinterpret_cast<float4*>(out + ((size_t)gi * N_ + gj) * 4) = r;
        }
}

// ---------------- 6. fixup: recompute every edge-touched cell with its a ----
// One warp per (c,e) edge instance. Duplicates rewrite identical values.
__global__ void __launch_bounds__(256) k_fixup(const int* __restrict__ ei,
                                               const float* __restrict__ We1,
                                               const float* __restrict__ We2,
                                               const float* __restrict__ be2,
                                               float* __restrict__ out) {
    __shared__ float W1c[4][256];   // We1 rows 0..3 (a coefficients)
    __shared__ float W2T[4][256];   // We2 transposed
    int tid = threadIdx.x;
#pragma unroll
    for (int m = 0; m < 4; m++) {
        int idx = m * 256 + tid;                    // 0..1023
        W1c[idx >> 8][idx & 255] = We1[idx];        // first 4*256 floats of We1
        W2T[idx >> 8][idx & 255] = We2[(idx & 255) * 4 + (idx >> 8)];
    }
    __syncthreads();

    int w = tid >> 5, lane = tid & 31;
    int eidx = blockIdx.x * 8 + w;                  // < 131072
    int c = eidx >> 15;
    int e = eidx & (E_ - 1);
    int i = ei[c * 2 * E_ + e];
    int j = ei[c * 2 * E_ + E_ + e];

    float4 a4 = *reinterpret_cast<const float4*>(g_a + (i * N_ + j) * 4);
    const float* Pr = g_P + i * 256;
    const float* Qr = g_Q + j * 256;

    float a0 = 0.f, a1 = 0.f, a2 = 0.f, a3 = 0.f;
#pragma unroll
    for (int hh = 0; hh < 8; hh++) {
        int h = hh * 32 + lane;
        float t = Pr[h] + Qr[h]
                + a4.x * W1c[0][h] + a4.y * W1c[1][h]
                + a4.z * W1c[2][h] + a4.w * W1c[3][h];
        t = fmaxf(t, 0.f);
        a0 += t * W2T[0][h];
        a1 += t * W2T[1][h];
        a2 += t * W2T[2][h];
        a3 += t * W2T[3][h];
    }
#pragma unroll
    for (int off = 16; off > 0; off >>= 1) {
        a0 += __shfl_xor_sync(0xffffffffu, a0, off);
        a1 += __shfl_xor_sync(0xffffffffu, a1, off);
        a2 += __shfl_xor_sync(0xffffffffu, a2, off);
        a3 += __shfl_xor_sync(0xffffffffu, a3, off);
    }
    if (lane == 0) {
        float4 r = make_float4(a0 + be2[0], a1 + be2[1], a2 + be2[2], a3 + be2[3]);
        *reinterpret_cast<float4*>(out + ((size_t)i * N_ + j) * 4) = r;
    }
}

// ---------------- launch ----------------------------------------------------
extern "C" void kernel_launch(void* const* d_in, const int* in_sizes, int n_in,
                              void* d_out, int out_size) {
    const float* x   = (const float*)d_in[0];
    const int*   ei  = (const int*)  d_in[1];
    const float* ew  = (const float*)d_in[2];
    const float* Wn1 = (const float*)d_in[3];
    const float* bn1 = (const float*)d_in[4];
    const float* Wn2 = (const float*)d_in[5];
    const float* bn2 = (const float*)d_in[6];
    const float* We1 = (const float*)d_in[7];
    const float* be1 = (const float*)d_in[8];
    const float* We2 = (const float*)d_in[9];
    const float* be2 = (const float*)d_in[10];
    const float* eps = (const float*)d_in[11];
    float* out = (float*)d_out;

    const int DENSE_SMEM = (2 * 32 * PSTR) * 4 + 512 * 8;   // 70144 bytes
    cudaFuncSetAttribute(k_dense, cudaFuncAttributeMaxDynamicSharedMemorySize,
                         DENSE_SMEM);

    k_zero_a<<<(N_ * N_ * C_ / 4) / 256, 256>>>();
    k_scatter<<<(C_ * E_) / 256, 256>>>(ei, ew);
    k_agg<<<N_ / 8, 256>>>(x, eps);
    k_node<<<N_ / 8, 256>>>(Wn1, bn1, Wn2, bn2, We1, be1);
    k_dense<<<dim3(N_ / 32, N_ / 32), 256, DENSE_SMEM>>>(We2, be2, out);
    k_fixup<<<(C_ * E_) / 8, 256>>>(ei, We1, We2, be2, out);
}

// round 15
// speedup vs baseline: 1.5043x; 1.1101x over previous
#include <cuda_runtime.h>

#define N_ 1024
#define F_ 64
#define C_ 4
#define E_ 32768
#define H_ 256

typedef unsigned long long ull;

// ---------------- scratch (device globals; no runtime allocation) ----------
__device__ float g_a[N_ * N_ * C_];   // a[i][j][c]  (i=src, j=tgt)  16 MB
__device__ float g_h[N_ * H_];        // stage-1 concat features [n][c*64+f]
__device__ float g_P[N_ * H_];        // be1 + x_next @ We1[rows 4..67]
__device__ float g_Q[N_ * H_];        //       x_next @ We1[rows 68..131]

// ---------------- f32x2 helpers --------------------------------------------
__device__ __forceinline__ ull pack2(float x, float y) {
    ull r;
    asm("mov.b64 %0, {%1,%2};" : "=l"(r) : "r"(__float_as_uint(x)), "r"(__float_as_uint(y)));
    return r;
}
__device__ __forceinline__ void fma2(ull& acc, ull a, ull b) {
    asm("fma.rn.f32x2 %0, %1, %2, %0;" : "+l"(acc) : "l"(a), "l"(b));
}
__device__ __forceinline__ ull add2(ull a, ull b) {
    ull r;
    asm("add.rn.f32x2 %0, %1, %2;" : "=l"(r) : "l"(a), "l"(b));
    return r;
}
__device__ __forceinline__ float lo_f(ull v) {
    return __uint_as_float((unsigned)(v & 0xffffffffull));
}
__device__ __forceinline__ float hi_f(ull v) {
    return __uint_as_float((unsigned)(v >> 32));
}

// ---------------- 1. zero dense adjacency ----------------------------------
__global__ void k_zero_a() {
    int idx = blockIdx.x * 256 + threadIdx.x;       // 1M float4s
    reinterpret_cast<float4*>(g_a)[idx] = make_float4(0.f, 0.f, 0.f, 0.f);
}

// ---------------- 2. scatter edges into dense a ----------------------------
__global__ void k_scatter(const int* __restrict__ ei, const float* __restrict__ ew) {
    int idx = blockIdx.x * 256 + threadIdx.x;       // < C*E = 131072
    int c = idx >> 15;                              // E = 2^15
    int e = idx & (E_ - 1);
    int s = ei[c * 2 * E_ + e];                     // edge_index[c][0][e] = src
    int t = ei[c * 2 * E_ + E_ + e];                // edge_index[c][1][e] = tgt
    float w = ew[c * E_ + e];
    atomicAdd(&g_a[(s * N_ + t) * C_ + c], w);
}

// ---------------- 3. agg[c][t][f] = sum_s a[s][t][c] * x[s][f]; + self -----
// 128 blocks x 8 targets. Register double-buffer: LDGs for tile t+1 issue
// before the compute phase of tile t, hiding DRAM latency behind FMA work.
__global__ void __launch_bounds__(256) k_agg(const float* __restrict__ x,
                                             const float* __restrict__ eps_p) {
    __shared__ __align__(16) float as[64][32];   // [ss][c*8 + t_local] (permuted)
    __shared__ __align__(16) float xs[64][64];   // [ss][f]
    int tid = threadIdx.x;
    int c = tid >> 6, f = tid & 63;
    int t0 = blockIdx.x * 8;

    ull acc[4];
    ull z = pack2(0.f, 0.f);
#pragma unroll
    for (int j = 0; j < 4; j++) acc[j] = z;

    float  ra[8];
    float4 rx[4];
    const float4* x4 = reinterpret_cast<const float4*>(x);

#define LOAD_REGS(S0)                                                        \
    {                                                                        \
        _Pragma("unroll")                                                    \
        for (int m = 0; m < 8; m++) {                                        \
            int elem = m * 256 + tid;                                        \
            int ss = elem >> 5, q = elem & 31;                               \
            ra[m] = g_a[(((S0) + ss) * N_ + t0 + (q & 7)) * 4 + (q >> 3)];   \
        }                                                                    \
        _Pragma("unroll")                                                    \
        for (int m = 0; m < 4; m++) {                                        \
            int idx4 = m * 256 + tid;                                        \
            rx[m] = x4[((S0) + (idx4 >> 4)) * 16 + (idx4 & 15)];             \
        }                                                                    \
    }

    LOAD_REGS(0);
    for (int s0 = 0; s0 < N_; s0 += 64) {
        // store current tile regs -> smem
#pragma unroll
        for (int m = 0; m < 8; m++) {
            int elem = m * 256 + tid;
            as[elem >> 5][elem & 31] = ra[m];
        }
#pragma unroll
        for (int m = 0; m < 4; m++) {
            int idx4 = m * 256 + tid;
            *reinterpret_cast<float4*>(&xs[idx4 >> 4][(idx4 & 15) * 4]) = rx[m];
        }
        __syncthreads();
        // prefetch next tile while computing this one
        if (s0 + 64 < N_) LOAD_REGS(s0 + 64);
#pragma unroll 8
        for (int ss = 0; ss < 64; ss++) {
            float xv = xs[ss][f];
            ull xv2 = pack2(xv, xv);
            const ull* ap = (const ull*)&as[ss][c * 8];
            fma2(acc[0], ap[0], xv2);
            fma2(acc[1], ap[1], xv2);
            fma2(acc[2], ap[2], xv2);
            fma2(acc[3], ap[3], xv2);
        }
        __syncthreads();
    }
#undef LOAD_REGS
    float se = 1.0f + *eps_p;
#pragma unroll
    for (int j = 0; j < 4; j++) {
        int t = t0 + 2 * j;
        g_h[t * 256 + c * 64 + f]       = lo_f(acc[j]) + se * x[t * 64 + f];
        g_h[(t + 1) * 256 + c * 64 + f] = hi_f(acc[j]) + se * x[(t + 1) * 64 + f];
    }
}

// ---------------- 4. fused node MLP (256 blocks x 4 rows) -------------------
// hid=relu(h@Wn1+bn1); xn=hid@Wn2+bn2; P=be1+xn@We1[4:68]; Q=xn@We1[68:132].
// Weight LDGs are chunk-prefetched into registers (16 in flight) to force MLP.
__global__ void __launch_bounds__(256) k_node(const float* __restrict__ Wn1,
                                              const float* __restrict__ bn1,
                                              const float* __restrict__ Wn2,
                                              const float* __restrict__ bn2,
                                              const float* __restrict__ We1,
                                              const float* __restrict__ be1) {
    __shared__ __align__(16) float hT[256][6];     // h transposed: [k][row]
    __shared__ __align__(16) float hidT[256][6];   // hidden transposed
    __shared__ __align__(16) float xT[64][6];      // x_next transposed: [f][row]
    __shared__ ull xpart[2][64][2];                // stage-2 k-split partials
    int tid = threadIdx.x;
    int n0 = blockIdx.x * 4;

    // load + transpose 4 rows of h
#pragma unroll
    for (int m = 0; m < 4; m++) {
        int elem = m * 256 + tid;
        int r = elem >> 8, k = elem & 255;
        hT[k][r] = g_h[(n0 + r) * 256 + k];
    }
    __syncthreads();

    // ---- stage 1: hid = relu(h @ Wn1 + bn1); this thread owns h-col tid ----
    {
        ull acc0 = pack2(0.f, 0.f), acc1 = acc0;
        const float* wp = Wn1 + tid;
#pragma unroll 1
        for (int k0 = 0; k0 < 256; k0 += 16) {
            float w[16];
#pragma unroll
            for (int u = 0; u < 16; u++) w[u] = wp[(k0 + u) * 256];
#pragma unroll
            for (int u = 0; u < 16; u++) {
                ull w2 = pack2(w[u], w[u]);
                const ull* hp = (const ull*)&hT[k0 + u][0];
                fma2(acc0, hp[0], w2);
                fma2(acc1, hp[1], w2);
            }
        }
        float b = bn1[tid];
        hidT[tid][0] = fmaxf(lo_f(acc0) + b, 0.f);
        hidT[tid][1] = fmaxf(hi_f(acc0) + b, 0.f);
        hidT[tid][2] = fmaxf(lo_f(acc1) + b, 0.f);
        hidT[tid][3] = fmaxf(hi_f(acc1) + b, 0.f);
    }
    __syncthreads();

    // ---- stage 2: x_next = hid @ Wn2 + bn2; (f, row-pair, k-half) ----
    {
        int f = tid & 63, pg = (tid >> 6) & 1, kh = tid >> 7;
        ull acc = pack2(0.f, 0.f);
        const float* wp = Wn2 + f;
        int kbase = kh * 128;
#pragma unroll 1
        for (int k0 = 0; k0 < 128; k0 += 16) {
            float w[16];
#pragma unroll
            for (int u = 0; u < 16; u++) w[u] = wp[(kbase + k0 + u) * 64];
#pragma unroll
            for (int u = 0; u < 16; u++) {
                ull w2 = pack2(w[u], w[u]);
                const ull* hp = (const ull*)&hidT[kbase + k0 + u][2 * pg];
                fma2(acc, hp[0], w2);
            }
        }
        xpart[kh][f][pg] = acc;
        __syncthreads();
        if (kh == 0) {
            ull s = add2(xpart[0][f][pg], xpart[1][f][pg]);
            float b = bn2[f];
            xT[f][2 * pg]     = lo_f(s) + b;
            xT[f][2 * pg + 1] = hi_f(s) + b;
        }
    }
    __syncthreads();

    // ---- stage 3: P = be1 + xn@We1[4:68]; Q = xn@We1[68:132]; h-col=tid ----
    {
        ull aP0 = pack2(0.f, 0.f), aP1 = aP0, aQ0 = aP0, aQ1 = aP0;
        const float* wp1 = We1 + 4 * 256 + tid;
        const float* wpq = We1 + 68 * 256 + tid;
#pragma unroll 1
        for (int f0 = 0; f0 < 64; f0 += 8) {
            float w1[8], wq[8];
#pragma unroll
            for (int u = 0; u < 8; u++) {
                w1[u] = wp1[(f0 + u) * 256];
                wq[u] = wpq[(f0 + u) * 256];
            }
#pragma unroll
            for (int u = 0; u < 8; u++) {
                const ull* xp = (const ull*)&xT[f0 + u][0];
                ull x0 = xp[0], x1 = xp[1];
                ull p2 = pack2(w1[u], w1[u]);
                ull q2 = pack2(wq[u], wq[u]);
                fma2(aP0, x0, p2);
                fma2(aP1, x1, p2);
                fma2(aQ0, x0, q2);
                fma2(aQ1, x1, q2);
            }
        }
        float b = be1[tid];
        g_P[(n0 + 0) * 256 + tid] = lo_f(aP0) + b;
        g_P[(n0 + 1) * 256 + tid] = hi_f(aP0) + b;
        g_P[(n0 + 2) * 256 + tid] = lo_f(aP1) + b;
        g_P[(n0 + 3) * 256 + tid] = hi_f(aP1) + b;
        g_Q[(n0 + 0) * 256 + tid] = lo_f(aQ0);
        g_Q[(n0 + 1) * 256 + tid] = hi_f(aQ0);
        g_Q[(n0 + 2) * 256 + tid] = lo_f(aQ1);
        g_Q[(n0 + 3) * 256 + tid] = hi_f(aQ1);
    }
}

// ---------------- 5. dense pass: out[i,j,:] = relu(P_i+Q_j) @ We2 + be2 -----
#define PSTR 258   // padded row stride (floats): 8B aligned, <=2-way conflicts
__global__ void __launch_bounds__(256) k_dense(const float* __restrict__ We2,
                                               const float* __restrict__ be2,
                                               float* __restrict__ out) {
    extern __shared__ float sm[];
    float* Ps = sm;                                 // 32 * 258
    float* Qs = sm + 32 * PSTR;                     // 32 * 258
    ull* W2p = (ull*)(sm + 2 * 32 * PSTR);          // 128 h2 x 4 o
    int tid = threadIdx.x;
    int ibase = blockIdx.x * 32, jbase = blockIdx.y * 32;

#pragma unroll
    for (int m = 0; m < 32; m++) {
        int idx = m * 256 + tid;                    // 0..8191
        int r = idx >> 8, k = idx & 255;
        Ps[r * PSTR + k] = g_P[(ibase + r) * 256 + k];
        Qs[r * PSTR + k] = g_Q[(jbase + r) * 256 + k];
    }
    for (int u = tid; u < 512; u += 256) {
        int h2 = u >> 2, o = u & 3;
        W2p[u] = pack2(We2[(2 * h2) * 4 + o], We2[(2 * h2 + 1) * 4 + o]);
    }
    __syncthreads();

    int jg = tid & 15, ig = tid >> 4;               // 2 i's x 2 j's per thread
    const float2* PA = (const float2*)(Ps + (2 * ig) * PSTR);
    const float2* PB = (const float2*)(Ps + (2 * ig + 1) * PSTR);
    const float2* QA = (const float2*)(Qs + (2 * jg) * PSTR);
    const float2* QB = (const float2*)(Qs + (2 * jg + 1) * PSTR);

    ull acc[4][4];                                  // [pair 2*di+dj][o]
    ull z = pack2(0.f, 0.f);
#pragma unroll
    for (int p = 0; p < 4; p++)
#pragma unroll
        for (int o = 0; o < 4; o++) acc[p][o] = z;

#pragma unroll 4
    for (int h2 = 0; h2 < 128; h2++) {
        float2 pa = PA[h2], pb = PB[h2], qa = QA[h2], qb = QB[h2];
        ull w0 = W2p[h2 * 4 + 0];
        ull w1 = W2p[h2 * 4 + 1];
        ull w2 = W2p[h2 * 4 + 2];
        ull w3 = W2p[h2 * 4 + 3];
#define DO_PAIR(PV, QV, A)                                          \
        {                                                           \
            float rx = fmaxf(PV.x + QV.x, 0.f);                     \
            float ry = fmaxf(PV.y + QV.y, 0.f);                     \
            ull r2 = pack2(rx, ry);                                 \
            fma2(A[0], r2, w0); fma2(A[1], r2, w1);                 \
            fma2(A[2], r2, w2); fma2(A[3], r2, w3);                 \
        }
        DO_PAIR(pa, qa, acc[0]);
        DO_PAIR(pa, qb, acc[1]);
        DO_PAIR(pb, qa, acc[2]);
        DO_PAIR(pb, qb, acc[3]);
#undef DO_PAIR
    }

    float b0 = be2[0], b1 = be2[1], b2v = be2[2], b3 = be2[3];
#pragma unroll
    for (int di = 0; di < 2; di++)
#pragma unroll
        for (int dj = 0; dj < 2; dj++) {
            int p = di * 2 + dj;
            int gi = ibase + 2 * ig + di;
            int gj = jbase + 2 * jg + dj;
            float4 r;
            r.x = lo_f(acc[p][0]) + hi_f(acc[p][0]) + b0;
            r.y = lo_f(acc[p][1]) + hi_f(acc[p][1]) + b1;
            r.z = lo_f(acc[p][2]) + hi_f(acc[p][2]) + b2v;
            r.w = lo_f(acc[p][3]) + hi_f(acc[p][3]) + b3;
            *reinterpret_cast<float4*>(out + ((size_t)gi * N_ + gj) * 4) = r;
        }
}

// ---------------- 6. fixup: recompute every edge-touched cell with its a ----
// One warp per (c,e) edge instance. Duplicates rewrite identical values.
__global__ void __launch_bounds__(256) k_fixup(const int* __restrict__ ei,
                                               const float* __restrict__ We1,
                                               const float* __restrict__ We2,
                                               const float* __restrict__ be2,
                                               float* __restrict__ out) {
    __shared__ float W1c[4][256];   // We1 rows 0..3 (a coefficients)
    __shared__ float W2T[4][256];   // We2 transposed
    int tid = threadIdx.x;
#pragma unroll
    for (int m = 0; m < 4; m++) {
        int idx = m * 256 + tid;                    // 0..1023
        W1c[idx >> 8][idx & 255] = We1[idx];        // first 4*256 floats of We1
        W2T[idx >> 8][idx & 255] = We2[(idx & 255) * 4 + (idx >> 8)];
    }
    __syncthreads();

    int w = tid >> 5, lane = tid & 31;
    int eidx = blockIdx.x * 8 + w;                  // < 131072
    int c = eidx >> 15;
    int e = eidx & (E_ - 1);
    int i = ei[c * 2 * E_ + e];
    int j = ei[c * 2 * E_ + E_ + e];

    float4 a4 = *reinterpret_cast<const float4*>(g_a + (i * N_ + j) * 4);
    const float* Pr = g_P + i * 256;
    const float* Qr = g_Q + j * 256;

    float a0 = 0.f, a1 = 0.f, a2 = 0.f, a3 = 0.f;
#pragma unroll
    for (int hh = 0; hh < 8; hh++) {
        int h = hh * 32 + lane;
        float t = Pr[h] + Qr[h]
                + a4.x * W1c[0][h] + a4.y * W1c[1][h]
                + a4.z * W1c[2][h] + a4.w * W1c[3][h];
        t = fmaxf(t, 0.f);
        a0 += t * W2T[0][h];
        a1 += t * W2T[1][h];
        a2 += t * W2T[2][h];
        a3 += t * W2T[3][h];
    }
#pragma unroll
    for (int off = 16; off > 0; off >>= 1) {
        a0 += __shfl_xor_sync(0xffffffffu, a0, off);
        a1 += __shfl_xor_sync(0xffffffffu, a1, off);
        a2 += __shfl_xor_sync(0xffffffffu, a2, off);
        a3 += __shfl_xor_sync(0xffffffffu, a3, off);
    }
    if (lane == 0) {
        float4 r = make_float4(a0 + be2[0], a1 + be2[1], a2 + be2[2], a3 + be2[3]);
        *reinterpret_cast<float4*>(out + ((size_t)i * N_ + j) * 4) = r;
    }
}

// ---------------- launch ----------------------------------------------------
extern "C" void kernel_launch(void* const* d_in, const int* in_sizes, int n_in,
                              void* d_out, int out_size) {
    const float* x   = (const float*)d_in[0];
    const int*   ei  = (const int*)  d_in[1];
    const float* ew  = (const float*)d_in[2];
    const float* Wn1 = (const float*)d_in[3];
    const float* bn1 = (const float*)d_in[4];
    const float* Wn2 = (const float*)d_in[5];
    const float* bn2 = (const float*)d_in[6];
    const float* We1 = (const float*)d_in[7];
    const float* be1 = (const float*)d_in[8];
    const float* We2 = (const float*)d_in[9];
    const float* be2 = (const float*)d_in[10];
    const float* eps = (const float*)d_in[11];
    float* out = (float*)d_out;

    const int DENSE_SMEM = (2 * 32 * PSTR) * 4 + 512 * 8;   // 70144 bytes
    cudaFuncSetAttribute(k_dense, cudaFuncAttributeMaxDynamicSharedMemorySize,
                         DENSE_SMEM);

    k_zero_a<<<(N_ * N_ * C_ / 4) / 256, 256>>>();
    k_scatter<<<(C_ * E_) / 256, 256>>>(ei, ew);
    k_agg<<<N_ / 8, 256>>>(x, eps);
    k_node<<<N_ / 4, 256>>>(Wn1, bn1, Wn2, bn2, We1, be1);
    k_dense<<<dim3(N_ / 32, N_ / 32), 256, DENSE_SMEM>>>(We2, be2, out);
    k_fixup<<<(C_ * E_) / 8, 256>>>(ei, We1, We2, be2, out);
}

// round 17
// speedup vs baseline: 1.5424x; 1.0253x over previous
#include <cuda_runtime.h>

#define N_ 1024
#define F_ 64
#define C_ 4
#define E_ 32768
#define H_ 256

typedef unsigned long long ull;

// ---------------- scratch (device globals; no runtime allocation) ----------
__device__ float g_a[N_ * N_ * C_];   // a[i][j][c]  (i=src, j=tgt)  16 MB
__device__ float g_h[N_ * H_];        // stage-1 concat features [n][c*64+f]
__device__ float g_P[N_ * H_];        // be1 + x_next @ We1[rows 4..67]
__device__ float g_Q[N_ * H_];        //       x_next @ We1[rows 68..131]

// ---------------- f32x2 helpers --------------------------------------------
__device__ __forceinline__ ull pack2(float x, float y) {
    ull r;
    asm("mov.b64 %0, {%1,%2};" : "=l"(r) : "r"(__float_as_uint(x)), "r"(__float_as_uint(y)));
    return r;
}
__device__ __forceinline__ void fma2(ull& acc, ull a, ull b) {
    asm("fma.rn.f32x2 %0, %1, %2, %0;" : "+l"(acc) : "l"(a), "l"(b));
}
__device__ __forceinline__ ull add2(ull a, ull b) {
    ull r;
    asm("add.rn.f32x2 %0, %1, %2;" : "=l"(r) : "l"(a), "l"(b));
    return r;
}
__device__ __forceinline__ float lo_f(ull v) {
    return __uint_as_float((unsigned)(v & 0xffffffffull));
}
__device__ __forceinline__ float hi_f(ull v) {
    return __uint_as_float((unsigned)(v >> 32));
}

// ---------------- cp.async helpers ------------------------------------------
__device__ __forceinline__ void cp16(void* smem, const void* gmem) {
    unsigned s = (unsigned)__cvta_generic_to_shared(smem);
    asm volatile("cp.async.cg.shared.global [%0], [%1], 16;" :: "r"(s), "l"(gmem));
}
__device__ __forceinline__ void cp_commit() {
    asm volatile("cp.async.commit_group;");
}
template <int NN>
__device__ __forceinline__ void cp_wait() {
    asm volatile("cp.async.wait_group %0;" :: "n"(NN));
}

// ---------------- 1. zero dense adjacency ----------------------------------
__global__ void k_zero_a() {
    int idx = blockIdx.x * 256 + threadIdx.x;       // 1M float4s
    reinterpret_cast<float4*>(g_a)[idx] = make_float4(0.f, 0.f, 0.f, 0.f);
}

// ---------------- 2. scatter edges into dense a ----------------------------
__global__ void k_scatter(const int* __restrict__ ei, const float* __restrict__ ew) {
    int idx = blockIdx.x * 256 + threadIdx.x;       // < C*E = 131072
    int c = idx >> 15;                              // E = 2^15
    int e = idx & (E_ - 1);
    int s = ei[c * 2 * E_ + e];                     // edge_index[c][0][e] = src
    int t = ei[c * 2 * E_ + E_ + e];                // edge_index[c][1][e] = tgt
    float w = ew[c * E_ + e];
    atomicAdd(&g_a[(s * N_ + t) * C_ + c], w);
}

// ---------------- 3. agg[c][t][f] = sum_s a[s][t][c] * x[s][f]; + self -----
// 256 blocks x 4 targets, cp.async double-buffered smem pipeline.
// Thread owns (tl = tid>>6, f = tid&63); accumulates c-PAIRS with FFMA2.
// a smem layout [ss][tl*4 + c] = literal byte order of g_a (c fastest).
__global__ void __launch_bounds__(256) k_agg(const float* __restrict__ x,
                                             const float* __restrict__ eps_p) {
    __shared__ __align__(16) float a_s[2][64][16];   // 4KB per stage
    __shared__ __align__(16) float x_s[2][64][64];   // 16KB per stage
    int tid = threadIdx.x;
    int tl = tid >> 6, f = tid & 63;                 // tl uniform per warp
    int t0 = blockIdx.x * 4;

    ull accA = pack2(0.f, 0.f), accB = accA;

#define AGG_CP(TILE, BUF)                                                     \
    {                                                                         \
        int s0 = (TILE) * 64;                                                 \
        _Pragma("unroll")                                                     \
        for (int m = 0; m < 4; m++) {                                         \
            int idx = m * 256 + tid;                                          \
            int ss = idx >> 4, seg = idx & 15;                                \
            cp16(&x_s[BUF][ss][seg * 4], x + (s0 + ss) * 64 + seg * 4);       \
        }                                                                     \
        {                                                                     \
            int ss = tid >> 2, part = tid & 3;                                \
            cp16(&a_s[BUF][ss][part * 4],                                     \
                 g_a + (s0 + ss) * (N_ * 4) + t0 * 4 + part * 4);             \
        }                                                                     \
    }

    AGG_CP(0, 0);
    cp_commit();
    for (int tile = 0; tile < 16; tile++) {
        int buf = tile & 1;
        if (tile < 15) {
            AGG_CP(tile + 1, (tile + 1) & 1);
            cp_commit();
            cp_wait<1>();
        } else {
            cp_wait<0>();
        }
        __syncthreads();
#pragma unroll 8
        for (int ss = 0; ss < 64; ss++) {
            float xv = x_s[buf][ss][f];
            ull xv2 = pack2(xv, xv);
            const ull* ap = (const ull*)&a_s[buf][ss][tl * 4];
            fma2(accA, ap[0], xv2);
            fma2(accB, ap[1], xv2);
        }
        __syncthreads();
    }
#undef AGG_CP

    float se = 1.0f + *eps_p;
    int t = t0 + tl;
    float xself = se; // multiplied below
    g_h[t * 256 + 0 * 64 + f] = lo_f(accA) + xself * x[t * 64 + f];
    g_h[t * 256 + 1 * 64 + f] = hi_f(accA) + xself * x[t * 64 + f];
    g_h[t * 256 + 2 * 64 + f] = lo_f(accB) + xself * x[t * 64 + f];
    g_h[t * 256 + 3 * 64 + f] = hi_f(accB) + xself * x[t * 64 + f];
}

// ---------------- 4. fused node MLP (128 blocks x 8 rows) -------------------
// hid=relu(h@Wn1+bn1); xn=hid@Wn2+bn2; P=be1+xn@We1[4:68]; Q=xn@We1[68:132].
// Stage-1 weights streamed via cp.async double buffer (8 chunks of 32 rows).
#define NODE_SMEM_FLOATS (2560 + 2560 + 640 + 2 * 32 * 256)
__global__ void __launch_bounds__(256) k_node(const float* __restrict__ Wn1,
                                              const float* __restrict__ bn1,
                                              const float* __restrict__ Wn2,
                                              const float* __restrict__ bn2,
                                              const float* __restrict__ We1,
                                              const float* __restrict__ be1) {
    extern __shared__ __align__(16) float ns[];
    float (*hT)[10]   = (float(*)[10])(ns);          // 256 x 10
    float (*hidT)[10] = (float(*)[10])(ns + 2560);   // 256 x 10
    float (*xT)[10]   = (float(*)[10])(ns + 5120);   // 64 x 10
    float* Ws         = ns + 5760;                    // 2 x 32 x 256
    int tid = threadIdx.x;
    int n0 = blockIdx.x * 8;

    // load + transpose 8 rows of h; also start first weight chunk
#define NODE_CP(CH, BUF)                                                      \
    {                                                                         \
        _Pragma("unroll")                                                     \
        for (int m = 0; m < 8; m++) {                                         \
            int idx = m * 256 + tid;                                          \
            cp16(Ws + (BUF) * 8192 + idx * 4, Wn1 + (CH) * 8192 + idx * 4);   \
        }                                                                     \
    }
    NODE_CP(0, 0);
    cp_commit();
#pragma unroll
    for (int m = 0; m < 8; m++) {
        int elem = m * 256 + tid;
        int r = elem >> 8, k = elem & 255;
        hT[k][r] = g_h[(n0 + r) * 256 + k];
    }
    __syncthreads();

    // ---- stage 1: hid = relu(h @ Wn1 + bn1); this thread owns h-col tid ----
    {
        ull acc0 = pack2(0.f, 0.f), acc1 = acc0, acc2 = acc0, acc3 = acc0;
        for (int ch = 0; ch < 8; ch++) {
            int buf = ch & 1;
            if (ch < 7) {
                NODE_CP(ch + 1, (ch + 1) & 1);
                cp_commit();
                cp_wait<1>();
            } else {
                cp_wait<0>();
            }
            __syncthreads();
            int k0 = ch * 32;
#pragma unroll
            for (int u = 0; u < 32; u++) {
                float w = Ws[buf * 8192 + u * 256 + tid];
                ull w2 = pack2(w, w);
                const ull* hp = (const ull*)&hT[k0 + u][0];
                fma2(acc0, hp[0], w2);
                fma2(acc1, hp[1], w2);
                fma2(acc2, hp[2], w2);
                fma2(acc3, hp[3], w2);
            }
            __syncthreads();
        }
        float b = bn1[tid];
        hidT[tid][0] = fmaxf(lo_f(acc0) + b, 0.f);
        hidT[tid][1] = fmaxf(hi_f(acc0) + b, 0.f);
        hidT[tid][2] = fmaxf(lo_f(acc1) + b, 0.f);
        hidT[tid][3] = fmaxf(hi_f(acc1) + b, 0.f);
        hidT[tid][4] = fmaxf(lo_f(acc2) + b, 0.f);
        hidT[tid][5] = fmaxf(hi_f(acc2) + b, 0.f);
        hidT[tid][6] = fmaxf(lo_f(acc3) + b, 0.f);
        hidT[tid][7] = fmaxf(hi_f(acc3) + b, 0.f);
    }
#undef NODE_CP
    __syncthreads();

    // ---- stage 2: x_next = hid @ Wn2 + bn2; thread owns (f, row-pair) ----
    {
        int f = tid & 63, rg = tid >> 6;            // rg uniform per warp
        ull acc = pack2(0.f, 0.f);
        const float* wp = Wn2 + f;
#pragma unroll 1
        for (int k0 = 0; k0 < 256; k0 += 16) {
            float w[16];
#pragma unroll
            for (int u = 0; u < 16; u++) w[u] = wp[(k0 + u) * 64];
#pragma unroll
            for (int u = 0; u < 16; u++) {
                ull w2 = pack2(w[u], w[u]);
                const ull* hp = (const ull*)&hidT[k0 + u][2 * rg];
                fma2(acc, hp[0], w2);
            }
        }
        float b = bn2[f];
        xT[f][2 * rg]     = lo_f(acc) + b;
        xT[f][2 * rg + 1] = hi_f(acc) + b;
    }
    __syncthreads();

    // ---- stage 3: P = be1 + xn@We1[4:68]; Q = xn@We1[68:132]; h-col=tid ----
    {
        ull aP[4], aQ[4];
        ull z = pack2(0.f, 0.f);
#pragma unroll
        for (int j = 0; j < 4; j++) { aP[j] = z; aQ[j] = z; }
        const float* wp1 = We1 + 4 * 256 + tid;
        const float* wpq = We1 + 68 * 256 + tid;
#pragma unroll 1
        for (int f0 = 0; f0 < 64; f0 += 8) {
            float w1[8], wq[8];
#pragma unroll
            for (int u = 0; u < 8; u++) {
                w1[u] = wp1[(f0 + u) * 256];
                wq[u] = wpq[(f0 + u) * 256];
            }
#pragma unroll
            for (int u = 0; u < 8; u++) {
                const ull* xp = (const ull*)&xT[f0 + u][0];
                ull p2 = pack2(w1[u], w1[u]);
                ull q2 = pack2(wq[u], wq[u]);
#pragma unroll
                for (int j = 0; j < 4; j++) {
                    fma2(aP[j], xp[j], p2);
                    fma2(aQ[j], xp[j], q2);
                }
            }
        }
        float b = be1[tid];
#pragma unroll
        for (int j = 0; j < 4; j++) {
            g_P[(n0 + 2 * j) * 256 + tid]     = lo_f(aP[j]) + b;
            g_P[(n0 + 2 * j + 1) * 256 + tid] = hi_f(aP[j]) + b;
            g_Q[(n0 + 2 * j) * 256 + tid]     = lo_f(aQ[j]);
            g_Q[(n0 + 2 * j + 1) * 256 + tid] = hi_f(aQ[j]);
        }
    }
}

// ---------------- 5. dense pass: out[i,j,:] = relu(P_i+Q_j) @ We2 + be2 -----
#define PSTR 258   // padded row stride (floats): 8B aligned, <=2-way conflicts
__global__ void __launch_bounds__(256) k_dense(const float* __restrict__ We2,
                                               const float* __restrict__ be2,
                                               float* __restrict__ out) {
    extern __shared__ float sm[];
    float* Ps = sm;                                 // 32 * 258
    float* Qs = sm + 32 * PSTR;                     // 32 * 258
    ull* W2p = (ull*)(sm + 2 * 32 * PSTR);          // 128 h2 x 4 o
    int tid = threadIdx.x;
    int ibase = blockIdx.x * 32, jbase = blockIdx.y * 32;

#pragma unroll
    for (int m = 0; m < 32; m++) {
        int idx = m * 256 + tid;                    // 0..8191
        int r = idx >> 8, k = idx & 255;
        Ps[r * PSTR + k] = g_P[(ibase + r) * 256 + k];
        Qs[r * PSTR + k] = g_Q[(jbase + r) * 256 + k];
    }
    for (int u = tid; u < 512; u += 256) {
        int h2 = u >> 2, o = u & 3;
        W2p[u] = pack2(We2[(2 * h2) * 4 + o], We2[(2 * h2 + 1) * 4 + o]);
    }
    __syncthreads();

    int jg = tid & 15, ig = tid >> 4;               // 2 i's x 2 j's per thread
    const ull* PA = (const ull*)(Ps + (2 * ig) * PSTR);
    const ull* PB = (const ull*)(Ps + (2 * ig + 1) * PSTR);
    const ull* QA = (const ull*)(Qs + (2 * jg) * PSTR);
    const ull* QB = (const ull*)(Qs + (2 * jg + 1) * PSTR);

    ull acc[4][4];                                  // [pair 2*di+dj][o]
    ull z = pack2(0.f, 0.f);
#pragma unroll
    for (int p = 0; p < 4; p++)
#pragma unroll
        for (int o = 0; o < 4; o++) acc[p][o] = z;

#pragma unroll 4
    for (int h2 = 0; h2 < 128; h2++) {
        ull pa = PA[h2], pb = PB[h2], qa = QA[h2], qb = QB[h2];
        ull w0 = W2p[h2 * 4 + 0];
        ull w1 = W2p[h2 * 4 + 1];
        ull w2 = W2p[h2 * 4 + 2];
        ull w3 = W2p[h2 * 4 + 3];
#define DO_PAIR(PV, QV, A)                                          \
        {                                                           \
            ull s = add2(PV, QV);                                   \
            float rx = fmaxf(lo_f(s), 0.f);                         \
            float ry = fmaxf(hi_f(s), 0.f);                         \
            ull r2 = pack2(rx, ry);                                 \
            fma2(A[0], r2, w0); fma2(A[1], r2, w1);                 \
            fma2(A[2], r2, w2); fma2(A[3], r2, w3);                 \
        }
        DO_PAIR(pa, qa, acc[0]);
        DO_PAIR(pa, qb, acc[1]);
        DO_PAIR(pb, qa, acc[2]);
        DO_PAIR(pb, qb, acc[3]);
#undef DO_PAIR
    }

    float b0 = be2[0], b1 = be2[1], b2v = be2[2], b3 = be2[3];
#pragma unroll
    for (int di = 0; di < 2; di++)
#pragma unroll
        for (int dj = 0; dj < 2; dj++) {
            int p = di * 2 + dj;
            int gi = ibase + 2 * ig + di;
            int gj = jbase + 2 * jg + dj;
            float4 r;
            r.x = lo_f(acc[p][0]) + hi_f(acc[p][0]) + b0;
            r.y = lo_f(acc[p][1]) + hi_f(acc[p][1]) + b1;
            r.z = lo_f(acc[p][2]) + hi_f(acc[p][2]) + b2v;
            r.w = lo_f(acc[p][3]) + hi_f(acc[p][3]) + b3;
            *reinterpret_cast<float4*>(out + ((size_t)gi * N_ + gj) * 4) = r;
        }
}

// ---------------- 6. fixup: recompute every edge-touched cell with its a ----
// One warp per 4 (c,e) edge instances. Duplicates rewrite identical values.
__global__ void __launch_bounds__(256) k_fixup(const int* __restrict__ ei,
                                               const float* __restrict__ We1,
                                               const float* __restrict__ We2,
                                               const float* __restrict__ be2,
                                               float* __restrict__ out) {
    __shared__ float W1c[4][256];   // We1 rows 0..3 (a coefficients)
    __shared__ float W2T[4][256];   // We2 transposed
    int tid = threadIdx.x;
#pragma unroll
    for (int m = 0; m < 4; m++) {
        int idx = m * 256 + tid;                    // 0..1023
        W1c[idx >> 8][idx & 255] = We1[idx];        // first 4*256 floats of We1
        W2T[idx >> 8][idx & 255] = We2[(idx & 255) * 4 + (idx >> 8)];
    }
    __syncthreads();

    int w = tid >> 5, lane = tid & 31;
    float b0 = be2[0], b1 = be2[1], b2v = be2[2], b3 = be2[3];

#pragma unroll 1
    for (int rr = 0; rr < 4; rr++) {
        int eidx = blockIdx.x * 32 + w * 4 + rr;    // < 131072
        int c = eidx >> 15;
        int e = eidx & (E_ - 1);
        int i = ei[c * 2 * E_ + e];
        int j = ei[c * 2 * E_ + E_ + e];

        float4 a4 = *reinterpret_cast<const float4*>(g_a + (i * N_ + j) * 4);
        const float* Pr = g_P + i * 256;
        const float* Qr = g_Q + j * 256;

        float a0 = 0.f, a1 = 0.f, a2 = 0.f, a3 = 0.f;
#pragma unroll
        for (int hh = 0; hh < 8; hh++) {
            int h = hh * 32 + lane;
            float t = Pr[h] + Qr[h]
                    + a4.x * W1c[0][h] + a4.y * W1c[1][h]
                    + a4.z * W1c[2][h] + a4.w * W1c[3][h];
            t = fmaxf(t, 0.f);
            a0 += t * W2T[0][h];
            a1 += t * W2T[1][h];
            a2 += t * W2T[2][h];
            a3 += t * W2T[3][h];
        }
#pragma unroll
        for (int off = 16; off > 0; off >>= 1) {
            a0 += __shfl_xor_sync(0xffffffffu, a0, off);
            a1 += __shfl_xor_sync(0xffffffffu, a1, off);
            a2 += __shfl_xor_sync(0xffffffffu, a2, off);
            a3 += __shfl_xor_sync(0xffffffffu, a3, off);
        }
        if (lane == 0) {
            float4 r = make_float4(a0 + b0, a1 + b1, a2 + b2v, a3 + b3);
            *reinterpret_cast<float4*>(out + ((size_t)i * N_ + j) * 4) = r;
        }
    }
}

// ---------------- launch ----------------------------------------------------
extern "C" void kernel_launch(void* const* d_in, const int* in_sizes, int n_in,
                              void* d_out, int out_size) {
    const float* x   = (const float*)d_in[0];
    const int*   ei  = (const int*)  d_in[1];
    const float* ew  = (const float*)d_in[2];
    const float* Wn1 = (const float*)d_in[3];
    const float* bn1 = (const float*)d_in[4];
    const float* Wn2 = (const float*)d_in[5];
    const float* bn2 = (const float*)d_in[6];
    const float* We1 = (const float*)d_in[7];
    const float* be1 = (const float*)d_in[8];
    const float* We2 = (const float*)d_in[9];
    const float* be2 = (const float*)d_in[10];
    const float* eps = (const float*)d_in[11];
    float* out = (float*)d_out;

    const int DENSE_SMEM = (2 * 32 * PSTR) * 4 + 512 * 8;   // 70144 bytes
    const int NODE_SMEM = NODE_SMEM_FLOATS * 4;             // 88576 bytes
    cudaFuncSetAttribute(k_dense, cudaFuncAttributeMaxDynamicSharedMemorySize,
                         DENSE_SMEM);
    cudaFuncSetAttribute(k_node, cudaFuncAttributeMaxDynamicSharedMemorySize,
                         NODE_SMEM);

    k_zero_a<<<(N_ * N_ * C_ / 4) / 256, 256>>>();
    k_scatter<<<(C_ * E_) / 256, 256>>>(ei, ew);
    k_agg<<<N_ / 4, 256>>>(x, eps);
    k_node<<<N_ / 8, 256, NODE_SMEM>>>(Wn1, bn1, Wn2, bn2, We1, be1);
    k_dense<<<dim3(N_ / 32, N_ / 32), 256, DENSE_SMEM>>>(We2, be2, out);
    k_fixup<<<(C_ * E_) / 32, 256>>>(ei, We1, We2, be2, out);
}